// round 3
// baseline (speedup 1.0000x reference)
#include <cuda_runtime.h>
#include <cuda_bf16.h>
#include <math.h>

// ---------------------------------------------------------------------------
// Problem constants
// ---------------------------------------------------------------------------
#define BATCH 4
#define SEQ   2048
#define DMODEL 1024
#define NHEAD 16
#define HDIM  64
#define ROWS  (BATCH * SEQ)          // 8192
#define EPS   1e-5f

// ---------------------------------------------------------------------------
// Scratch buffers (static device globals: allocation-free per harness rules)
// ---------------------------------------------------------------------------
__device__ float g_ln [ROWS * DMODEL];        // 32 MB  (reused ln1 & ln2)
__device__ float g_qkv[ROWS * 3 * DMODEL];    // 96 MB
__device__ float g_y  [ROWS * DMODEL];        // 32 MB  attention output
__device__ float g_x1 [ROWS * DMODEL];        // 32 MB  residual after attn
__device__ float g_h  [ROWS * 4 * DMODEL];    // 128 MB MLP hidden

// ---------------------------------------------------------------------------
// LayerNorm: one block per row (D=1024), 256 threads, float4 per thread
// ---------------------------------------------------------------------------
__device__ __forceinline__ float warp_sum(float v) {
#pragma unroll
    for (int o = 16; o > 0; o >>= 1) v += __shfl_xor_sync(0xffffffffu, v, o);
    return v;
}

__global__ __launch_bounds__(256) void ln_kernel(
    const float* __restrict__ x,
    const float* __restrict__ g,
    const float* __restrict__ b,
    float* __restrict__ out)
{
    const int row = blockIdx.x;
    const int tid = threadIdx.x;
    const float4 v = reinterpret_cast<const float4*>(x + (size_t)row * DMODEL)[tid];

    float s  = v.x + v.y + v.z + v.w;
    float ss = v.x*v.x + v.y*v.y + v.z*v.z + v.w*v.w;
    s  = warp_sum(s);
    ss = warp_sum(ss);

    __shared__ float red0[8], red1[8];
    const int wid = tid >> 5, lane = tid & 31;
    if (lane == 0) { red0[wid] = s; red1[wid] = ss; }
    __syncthreads();
    float ts = 0.f, tss = 0.f;
#pragma unroll
    for (int w = 0; w < 8; w++) { ts += red0[w]; tss += red1[w]; }

    const float mean = ts * (1.0f / DMODEL);
    const float var  = tss * (1.0f / DMODEL) - mean * mean;
    const float rstd = rsqrtf(var + EPS);

    const float4 gv = reinterpret_cast<const float4*>(g)[tid];
    const float4 bv = reinterpret_cast<const float4*>(b)[tid];
    float4 o;
    o.x = (v.x - mean) * rstd * gv.x + bv.x;
    o.y = (v.y - mean) * rstd * gv.y + bv.y;
    o.z = (v.z - mean) * rstd * gv.z + bv.z;
    o.w = (v.w - mean) * rstd * gv.w + bv.w;
    reinterpret_cast<float4*>(out + (size_t)row * DMODEL)[tid] = o;
}

// ---------------------------------------------------------------------------
// SGEMM: C[M,N] = A[M,K] @ B[K,N] (+ epilogue)
// 128x128 tile, BK=8, 256 threads, 8x8 microtile per thread.
// EPI: 0 = none, 1 = +res, 2 = gelu(acc + bias), 3 = acc + bias + res
// All dims multiples of 128 / K multiple of 8 — no bounds checks.
// ---------------------------------------------------------------------------
__device__ __forceinline__ float gelu_tanh(float x) {
    const float c0 = 0.7978845608028654f;  // sqrt(2/pi)
    const float c1 = 0.044715f;
    float t = tanhf(c0 * (x + c1 * x * x * x));
    return 0.5f * x * (1.0f + t);
}

template <int EPI>
__global__ __launch_bounds__(256) void sgemm_kernel(
    int M, int N, int K,
    const float* __restrict__ A,
    const float* __restrict__ B,
    const float* __restrict__ bias,
    const float* __restrict__ res,
    float* __restrict__ C)
{
    __shared__ float As[8][128];
    __shared__ float Bs[8][128];

    const int tid = threadIdx.x;
    const int tx = tid & 15;          // 0..15 -> N
    const int ty = tid >> 4;          // 0..15 -> M

    const int aRow = tid >> 1;            // 0..127
    const int aCol = (tid & 1) * 4;       // 0 or 4
    const int bRow = tid >> 5;            // 0..7
    const int bCol = (tid & 31) * 4;      // 0..124

    const float* Ag = A + (size_t)(blockIdx.y * 128) * K;
    const float* Bg = B + (size_t)(blockIdx.x * 128);

    float acc[8][8];
#pragma unroll
    for (int i = 0; i < 8; i++)
#pragma unroll
        for (int j = 0; j < 8; j++) acc[i][j] = 0.f;

    for (int k0 = 0; k0 < K; k0 += 8) {
        const float4 av = *reinterpret_cast<const float4*>(
            Ag + (size_t)aRow * K + k0 + aCol);
        As[aCol + 0][aRow] = av.x;
        As[aCol + 1][aRow] = av.y;
        As[aCol + 2][aRow] = av.z;
        As[aCol + 3][aRow] = av.w;

        const float4 bv = *reinterpret_cast<const float4*>(
            Bg + (size_t)(k0 + bRow) * N + bCol);
        *reinterpret_cast<float4*>(&Bs[bRow][bCol]) = bv;

        __syncthreads();
#pragma unroll
        for (int k = 0; k < 8; k++) {
            float ra[8], rb[8];
#pragma unroll
            for (int i = 0; i < 8; i++) ra[i] = As[k][ty * 8 + i];
#pragma unroll
            for (int j = 0; j < 8; j++) rb[j] = Bs[k][tx * 8 + j];
#pragma unroll
            for (int i = 0; i < 8; i++)
#pragma unroll
                for (int j = 0; j < 8; j++) acc[i][j] = fmaf(ra[i], rb[j], acc[i][j]);
        }
        __syncthreads();
    }

    const int row0 = blockIdx.y * 128 + ty * 8;
    const int col0 = blockIdx.x * 128 + tx * 8;

    float bvals[8];
    if (EPI == 2 || EPI == 3) {
#pragma unroll
        for (int j = 0; j < 8; j++) bvals[j] = bias[col0 + j];
    }

#pragma unroll
    for (int i = 0; i < 8; i++) {
        float* crow = C + (size_t)(row0 + i) * N + col0;
        const float* rrow = (EPI == 1 || EPI == 3)
                          ? res + (size_t)(row0 + i) * N + col0 : nullptr;
#pragma unroll
        for (int jj = 0; jj < 8; jj += 4) {
            float4 v;
            v.x = acc[i][jj + 0]; v.y = acc[i][jj + 1];
            v.z = acc[i][jj + 2]; v.w = acc[i][jj + 3];
            if (EPI == 2) {
                v.x = gelu_tanh(v.x + bvals[jj + 0]);
                v.y = gelu_tanh(v.y + bvals[jj + 1]);
                v.z = gelu_tanh(v.z + bvals[jj + 2]);
                v.w = gelu_tanh(v.w + bvals[jj + 3]);
            }
            if (EPI == 3) {
                v.x += bvals[jj + 0]; v.y += bvals[jj + 1];
                v.z += bvals[jj + 2]; v.w += bvals[jj + 3];
            }
            if (EPI == 1 || EPI == 3) {
                float4 r = *reinterpret_cast<const float4*>(rrow + jj);
                v.x += r.x; v.y += r.y; v.z += r.z; v.w += r.w;
            }
            *reinterpret_cast<float4*>(crow + jj) = v;
        }
    }
}

// ---------------------------------------------------------------------------
// Causal flash attention, fp32.
// Grid: (qtile 0..31, b*H 0..63). Block: 256 threads.
// Per block: 64 queries x hd=64. KV tiles of 64 with online softmax.
// smem: Qs, Ks, Vs, Ps each 64x65 floats (pad avoids worst conflicts).
// ---------------------------------------------------------------------------
#define ATT_STRIDE 65
#define ATT_SMEM   (4 * 64 * ATT_STRIDE * (int)sizeof(float))

__global__ __launch_bounds__(256) void attn_kernel(
    const float* __restrict__ qkv,
    float* __restrict__ y)
{
    extern __shared__ float sm[];
    float* Qs = sm;
    float* Ks = Qs + 64 * ATT_STRIDE;
    float* Vs = Ks + 64 * ATT_STRIDE;
    float* Ps = Vs + 64 * ATT_STRIDE;

    const int qt  = blockIdx.x;            // 0..31
    const int bh  = blockIdx.y;            // 0..63
    const int b   = bh >> 4;
    const int h   = bh & 15;
    const int tid = threadIdx.x;
    const int tx  = tid & 15;
    const int ty  = tid >> 4;

    const size_t rstr = 3 * DMODEL;        // qkv row stride
    const float* qbase = qkv + ((size_t)b * SEQ + qt * 64) * rstr + h * HDIM;
    const float* kbase = qkv + (size_t)b * SEQ * rstr + DMODEL     + h * HDIM;
    const float* vbase = qkv + (size_t)b * SEQ * rstr + 2 * DMODEL + h * HDIM;

    // load Q tile, scaled by 1/sqrt(hd)
#pragma unroll
    for (int i = 0; i < 4; i++) {
        int idx = tid + i * 256;
        int r = idx >> 4, c4 = (idx & 15) * 4;
        float4 v = *reinterpret_cast<const float4*>(qbase + (size_t)r * rstr + c4);
        Qs[r * ATT_STRIDE + c4 + 0] = v.x * 0.125f;
        Qs[r * ATT_STRIDE + c4 + 1] = v.y * 0.125f;
        Qs[r * ATT_STRIDE + c4 + 2] = v.z * 0.125f;
        Qs[r * ATT_STRIDE + c4 + 3] = v.w * 0.125f;
    }

    float m[4], l[4], o[4][4];
#pragma unroll
    for (int i = 0; i < 4; i++) {
        m[i] = -1e30f; l[i] = 0.f;
#pragma unroll
        for (int j = 0; j < 4; j++) o[i][j] = 0.f;
    }

    for (int kt = 0; kt <= qt; kt++) {
        __syncthreads();   // protect K/V/P reuse from previous iteration
#pragma unroll
        for (int i = 0; i < 4; i++) {
            int idx = tid + i * 256;
            int r = idx >> 4, c4 = (idx & 15) * 4;
            size_t grow = (size_t)(kt * 64 + r) * rstr + c4;
            float4 kv4 = *reinterpret_cast<const float4*>(kbase + grow);
            Ks[r * ATT_STRIDE + c4 + 0] = kv4.x;
            Ks[r * ATT_STRIDE + c4 + 1] = kv4.y;
            Ks[r * ATT_STRIDE + c4 + 2] = kv4.z;
            Ks[r * ATT_STRIDE + c4 + 3] = kv4.w;
            float4 vv4 = *reinterpret_cast<const float4*>(vbase + grow);
            Vs[r * ATT_STRIDE + c4 + 0] = vv4.x;
            Vs[r * ATT_STRIDE + c4 + 1] = vv4.y;
            Vs[r * ATT_STRIDE + c4 + 2] = vv4.z;
            Vs[r * ATT_STRIDE + c4 + 3] = vv4.w;
        }
        __syncthreads();

        // S = Q @ K^T  (64x64 tile, thread owns 4x4)
        float s[4][4];
#pragma unroll
        for (int i = 0; i < 4; i++)
#pragma unroll
            for (int j = 0; j < 4; j++) s[i][j] = 0.f;
#pragma unroll 8
        for (int k = 0; k < 64; k++) {
            float qr[4], kr[4];
#pragma unroll
            for (int i = 0; i < 4; i++) qr[i] = Qs[(ty * 4 + i) * ATT_STRIDE + k];
#pragma unroll
            for (int j = 0; j < 4; j++) kr[j] = Ks[(tx * 4 + j) * ATT_STRIDE + k];
#pragma unroll
            for (int i = 0; i < 4; i++)
#pragma unroll
                for (int j = 0; j < 4; j++) s[i][j] = fmaf(qr[i], kr[j], s[i][j]);
        }

        if (kt == qt) {   // causal mask on diagonal tile
#pragma unroll
            for (int i = 0; i < 4; i++)
#pragma unroll
                for (int j = 0; j < 4; j++)
                    if (tx * 4 + j > ty * 4 + i) s[i][j] = -1e30f;
        }

        // online softmax per row (reduce across tx: 16 lanes within warp half)
#pragma unroll
        for (int i = 0; i < 4; i++) {
            float mr = fmaxf(fmaxf(s[i][0], s[i][1]), fmaxf(s[i][2], s[i][3]));
#pragma unroll
            for (int off = 8; off > 0; off >>= 1)
                mr = fmaxf(mr, __shfl_xor_sync(0xffffffffu, mr, off));
            float mn = fmaxf(m[i], mr);
            float corr = __expf(m[i] - mn);
            float psum = 0.f;
#pragma unroll
            for (int j = 0; j < 4; j++) {
                s[i][j] = __expf(s[i][j] - mn);
                psum += s[i][j];
            }
#pragma unroll
            for (int off = 8; off > 0; off >>= 1)
                psum += __shfl_xor_sync(0xffffffffu, psum, off);
            l[i] = l[i] * corr + psum;
            m[i] = mn;
#pragma unroll
            for (int j = 0; j < 4; j++) {
                o[i][j] *= corr;
                Ps[(ty * 4 + i) * ATT_STRIDE + tx * 4 + j] = s[i][j];
            }
        }
        __syncthreads();

        // O += P @ V
#pragma unroll 8
        for (int k = 0; k < 64; k++) {
            float pr[4], vr[4];
#pragma unroll
            for (int i = 0; i < 4; i++) pr[i] = Ps[(ty * 4 + i) * ATT_STRIDE + k];
#pragma unroll
            for (int j = 0; j < 4; j++) vr[j] = Vs[k * ATT_STRIDE + tx * 4 + j];
#pragma unroll
            for (int i = 0; i < 4; i++)
#pragma unroll
                for (int j = 0; j < 4; j++) o[i][j] = fmaf(pr[i], vr[j], o[i][j]);
        }
    }

    // write normalized output to y[B,T,D] at head slice
#pragma unroll
    for (int i = 0; i < 4; i++) {
        float inv = 1.0f / l[i];
        size_t row = (size_t)b * SEQ + qt * 64 + ty * 4 + i;
#pragma unroll
        for (int j = 0; j < 4; j++)
            y[row * DMODEL + h * HDIM + tx * 4 + j] = o[i][j] * inv;
    }
}

// ---------------------------------------------------------------------------
// Launch
// ---------------------------------------------------------------------------
extern "C" void kernel_launch(void* const* d_in, const int* in_sizes, int n_in,
                              void* d_out, int out_size)
{
    const float* x      = (const float*)d_in[0];
    const float* w_attn = (const float*)d_in[1];
    const float* w_o    = (const float*)d_in[2];
    const float* ln1_g  = (const float*)d_in[3];
    const float* ln1_b  = (const float*)d_in[4];
    const float* ln2_g  = (const float*)d_in[5];
    const float* ln2_b  = (const float*)d_in[6];
    const float* w_fc   = (const float*)d_in[7];
    const float* b_fc   = (const float*)d_in[8];
    const float* w_proj = (const float*)d_in[9];
    const float* b_proj = (const float*)d_in[10];
    float* out = (float*)d_out;

    float *ln, *qkvp, *yp, *x1, *hp;
    cudaGetSymbolAddress((void**)&ln,   g_ln);
    cudaGetSymbolAddress((void**)&qkvp, g_qkv);
    cudaGetSymbolAddress((void**)&yp,   g_y);
    cudaGetSymbolAddress((void**)&x1,   g_x1);
    cudaGetSymbolAddress((void**)&hp,   g_h);

    cudaFuncSetAttribute(attn_kernel,
                         cudaFuncAttributeMaxDynamicSharedMemorySize, ATT_SMEM);

    // 1) ln1
    ln_kernel<<<ROWS, 256>>>(x, ln1_g, ln1_b, ln);
    // 2) qkv = ln1 @ w_attn        [8192 x 3072]
    sgemm_kernel<0><<<dim3(3 * DMODEL / 128, ROWS / 128), 256>>>(
        ROWS, 3 * DMODEL, DMODEL, ln, w_attn, nullptr, nullptr, qkvp);
    // 3) attention -> y
    attn_kernel<<<dim3(SEQ / 64, BATCH * NHEAD), 256, ATT_SMEM>>>(qkvp, yp);
    // 4) x1 = x + y @ w_o
    sgemm_kernel<1><<<dim3(DMODEL / 128, ROWS / 128), 256>>>(
        ROWS, DMODEL, DMODEL, yp, w_o, nullptr, x, x1);
    // 5) ln2
    ln_kernel<<<ROWS, 256>>>(x1, ln2_g, ln2_b, ln);
    // 6) h = gelu(ln2 @ w_fc + b_fc)   [8192 x 4096]
    sgemm_kernel<2><<<dim3(4 * DMODEL / 128, ROWS / 128), 256>>>(
        ROWS, 4 * DMODEL, DMODEL, ln, w_fc, b_fc, nullptr, hp);
    // 7) out = x1 + h @ w_proj + b_proj
    sgemm_kernel<3><<<dim3(DMODEL / 128, ROWS / 128), 256>>>(
        ROWS, DMODEL, 4 * DMODEL, hp, w_proj, b_proj, x1, out);
}

// round 4
// speedup vs baseline: 2.2798x; 2.2798x over previous
#include <cuda_runtime.h>
#include <cuda_bf16.h>
#include <math.h>
#include <stdint.h>

// ---------------------------------------------------------------------------
// Problem constants
// ---------------------------------------------------------------------------
#define BATCH 4
#define SEQ   2048
#define DMODEL 1024
#define NHEAD 16
#define HDIM  64
#define ROWS  (BATCH * SEQ)          // 8192
#define EPS   1e-5f

// ---------------------------------------------------------------------------
// Scratch buffers (static device globals: allocation-free per harness rules)
// ---------------------------------------------------------------------------
__device__ float g_ln [ROWS * DMODEL];        // 32 MB  (reused ln1 & ln2)
__device__ float g_qkv[ROWS * 3 * DMODEL];    // 96 MB
__device__ float g_y  [ROWS * DMODEL];        // 32 MB  attention output
__device__ float g_x1 [ROWS * DMODEL];        // 32 MB  residual after attn
__device__ float g_h  [ROWS * 4 * DMODEL];    // 128 MB MLP hidden

// ---------------------------------------------------------------------------
// LayerNorm: one block per row (D=1024), 256 threads, float4 per thread
// ---------------------------------------------------------------------------
__device__ __forceinline__ float warp_sum(float v) {
#pragma unroll
    for (int o = 16; o > 0; o >>= 1) v += __shfl_xor_sync(0xffffffffu, v, o);
    return v;
}

__global__ __launch_bounds__(256) void ln_kernel(
    const float* __restrict__ x,
    const float* __restrict__ g,
    const float* __restrict__ b,
    float* __restrict__ out)
{
    const int row = blockIdx.x;
    const int tid = threadIdx.x;
    const float4 v = reinterpret_cast<const float4*>(x + (size_t)row * DMODEL)[tid];

    float s  = v.x + v.y + v.z + v.w;
    float ss = v.x*v.x + v.y*v.y + v.z*v.z + v.w*v.w;
    s  = warp_sum(s);
    ss = warp_sum(ss);

    __shared__ float red0[8], red1[8];
    const int wid = tid >> 5, lane = tid & 31;
    if (lane == 0) { red0[wid] = s; red1[wid] = ss; }
    __syncthreads();
    float ts = 0.f, tss = 0.f;
#pragma unroll
    for (int w = 0; w < 8; w++) { ts += red0[w]; tss += red1[w]; }

    const float mean = ts * (1.0f / DMODEL);
    const float var  = tss * (1.0f / DMODEL) - mean * mean;
    const float rstd = rsqrtf(var + EPS);

    const float4 gv = reinterpret_cast<const float4*>(g)[tid];
    const float4 bv = reinterpret_cast<const float4*>(b)[tid];
    float4 o;
    o.x = (v.x - mean) * rstd * gv.x + bv.x;
    o.y = (v.y - mean) * rstd * gv.y + bv.y;
    o.z = (v.z - mean) * rstd * gv.z + bv.z;
    o.w = (v.w - mean) * rstd * gv.w + bv.w;
    reinterpret_cast<float4*>(out + (size_t)row * DMODEL)[tid] = o;
}

// ---------------------------------------------------------------------------
// TF32 tensor-core GEMM: C[M,N] = A[M,K] @ B[K,N] (+ epilogue)
// CTA tile 128x128, BK=16, 256 threads (8 warps as 2x4 -> 64x32 warp tiles).
// mma.sync.aligned.m16n8k8.row.col.f32.tf32.tf32.f32, fp32 accumulate.
// 2-stage cp.async pipeline. A smem [m][k] stride 20 (ldmatrix-friendly),
// B smem [k][n] stride 132.
// EPI: 0 = none, 1 = +res, 2 = gelu(acc + bias), 3 = acc + bias + res
// Dims: M,N multiples of 128; K multiple of 16.
// ---------------------------------------------------------------------------
__device__ __forceinline__ float gelu_tanh(float x) {
    const float c0 = 0.7978845608028654f;  // sqrt(2/pi)
    const float c1 = 0.044715f;
    float t = tanhf(c0 * (x + c1 * x * x * x));
    return 0.5f * x * (1.0f + t);
}

__device__ __forceinline__ unsigned f2tf32(float f) {
    unsigned r;
    asm("cvt.rna.tf32.f32 %0, %1;" : "=r"(r) : "f"(f));
    return r;
}

__device__ __forceinline__ void ldsm4(unsigned& r0, unsigned& r1,
                                      unsigned& r2, unsigned& r3, uint32_t a) {
    asm volatile("ldmatrix.sync.aligned.m8n8.x4.shared.b16 {%0,%1,%2,%3}, [%4];"
                 : "=r"(r0), "=r"(r1), "=r"(r2), "=r"(r3) : "r"(a));
}

__device__ __forceinline__ void mma_tf32(float* c,
                                         unsigned a0, unsigned a1,
                                         unsigned a2, unsigned a3,
                                         unsigned b0, unsigned b1) {
    asm volatile(
        "mma.sync.aligned.m16n8k8.row.col.f32.tf32.tf32.f32 "
        "{%0,%1,%2,%3}, {%4,%5,%6,%7}, {%8,%9}, {%0,%1,%2,%3};"
        : "+f"(c[0]), "+f"(c[1]), "+f"(c[2]), "+f"(c[3])
        : "r"(a0), "r"(a1), "r"(a2), "r"(a3), "r"(b0), "r"(b1));
}

#define AS_STRIDE 20
#define BS_STRIDE 132

template <int EPI>
__global__ __launch_bounds__(256) void tf32_gemm(
    int M, int N, int K,
    const float* __restrict__ A,
    const float* __restrict__ B,
    const float* __restrict__ bias,
    const float* __restrict__ res,
    float* __restrict__ C)
{
    __shared__ __align__(16) float As[2][128][AS_STRIDE];
    __shared__ __align__(16) float Bs[2][16][BS_STRIDE];

    const int tid  = threadIdx.x;
    const int lane = tid & 31;
    const int wid  = tid >> 5;
    const int m_w  = (wid >> 2) * 64;   // warp M origin (0 or 64)
    const int n_w  = (wid & 3) * 32;    // warp N origin

    // gmem -> smem thread mapping
    const int aRow  = tid >> 2;          // 0..63 (+64 second)
    const int aCol  = (tid & 3) * 4;
    const int bRowK = tid >> 5;          // 0..7  (+8 second)
    const int bColN = (tid & 31) * 4;

    const float* Ag = A + (size_t)(blockIdx.y * 128) * K;
    const float* Bg = B + (size_t)blockIdx.x * 128;

    float acc[4][4][4];
#pragma unroll
    for (int i = 0; i < 4; i++)
#pragma unroll
        for (int j = 0; j < 4; j++)
#pragma unroll
            for (int q = 0; q < 4; q++) acc[i][j][q] = 0.f;

    // ldmatrix source address (per-thread), constant across k-tiles
    const int lr  = lane & 7;
    const int lm8 = ((lane >> 3) & 1) * 8;
    const int lc4 = (lane >> 4) * 4;

    const int nk = K >> 4;

#define LOAD_STAGE(KT, ST)                                                       \
    do {                                                                         \
        const float* a0p = Ag + (size_t)aRow * K + (KT) * 16 + aCol;             \
        const float* a1p = a0p + (size_t)64 * K;                                 \
        uint32_t d0 = (uint32_t)__cvta_generic_to_shared(&As[ST][aRow][aCol]);   \
        uint32_t d1 = (uint32_t)__cvta_generic_to_shared(&As[ST][aRow+64][aCol]);\
        asm volatile("cp.async.cg.shared.global [%0], [%1], 16;" :: "r"(d0), "l"(a0p)); \
        asm volatile("cp.async.cg.shared.global [%0], [%1], 16;" :: "r"(d1), "l"(a1p)); \
        const float* b0p = Bg + (size_t)((KT) * 16 + bRowK) * N + bColN;         \
        const float* b1p = b0p + (size_t)8 * N;                                  \
        uint32_t e0 = (uint32_t)__cvta_generic_to_shared(&Bs[ST][bRowK][bColN]); \
        uint32_t e1 = (uint32_t)__cvta_generic_to_shared(&Bs[ST][bRowK+8][bColN]);\
        asm volatile("cp.async.cg.shared.global [%0], [%1], 16;" :: "r"(e0), "l"(b0p)); \
        asm volatile("cp.async.cg.shared.global [%0], [%1], 16;" :: "r"(e1), "l"(b1p)); \
        asm volatile("cp.async.commit_group;");                                  \
    } while (0)

    LOAD_STAGE(0, 0);

    for (int kt = 0; kt < nk; kt++) {
        const int st = kt & 1;
        if (kt + 1 < nk) {
            LOAD_STAGE(kt + 1, st ^ 1);
            asm volatile("cp.async.wait_group 1;");
        } else {
            asm volatile("cp.async.wait_group 0;");
        }
        __syncthreads();

#pragma unroll
        for (int ks = 0; ks < 2; ks++) {
            const int k8 = ks * 8;
            unsigned afr[4][4];
#pragma unroll
            for (int mf = 0; mf < 4; mf++) {
                uint32_t ad = (uint32_t)__cvta_generic_to_shared(
                    &As[st][m_w + mf * 16 + lr + lm8][k8 + lc4]);
                ldsm4(afr[mf][0], afr[mf][1], afr[mf][2], afr[mf][3], ad);
#pragma unroll
                for (int q = 0; q < 4; q++)
                    afr[mf][q] = f2tf32(__uint_as_float(afr[mf][q]));
            }
            unsigned bfr[4][2];
#pragma unroll
            for (int nf = 0; nf < 4; nf++) {
                const int nn = n_w + nf * 8 + (lane >> 2);
                bfr[nf][0] = f2tf32(Bs[st][k8 + (lane & 3)][nn]);
                bfr[nf][1] = f2tf32(Bs[st][k8 + 4 + (lane & 3)][nn]);
            }
#pragma unroll
            for (int mf = 0; mf < 4; mf++)
#pragma unroll
                for (int nf = 0; nf < 4; nf++)
                    mma_tf32(acc[mf][nf],
                             afr[mf][0], afr[mf][1], afr[mf][2], afr[mf][3],
                             bfr[nf][0], bfr[nf][1]);
        }
        __syncthreads();
    }
#undef LOAD_STAGE

    // ---------------- epilogue ----------------
    const int row0 = blockIdx.y * 128 + m_w;
    const int col0 = blockIdx.x * 128 + n_w;

#pragma unroll
    for (int mf = 0; mf < 4; mf++) {
#pragma unroll
        for (int nf = 0; nf < 4; nf++) {
            const int r = row0 + mf * 16 + (lane >> 2);
            const int c = col0 + nf * 8 + (lane & 3) * 2;
            float b0 = 0.f, b1 = 0.f;
            if (EPI == 2 || EPI == 3) { b0 = bias[c]; b1 = bias[c + 1]; }
#pragma unroll
            for (int half = 0; half < 2; half++) {
                const int rr = r + half * 8;
                float v0 = acc[mf][nf][half * 2 + 0];
                float v1 = acc[mf][nf][half * 2 + 1];
                if (EPI == 2) { v0 = gelu_tanh(v0 + b0); v1 = gelu_tanh(v1 + b1); }
                if (EPI == 3) { v0 += b0; v1 += b1; }
                if (EPI == 1 || EPI == 3) {
                    const float2 rv = *reinterpret_cast<const float2*>(
                        res + (size_t)rr * N + c);
                    v0 += rv.x; v1 += rv.y;
                }
                float2 o; o.x = v0; o.y = v1;
                *reinterpret_cast<float2*>(C + (size_t)rr * N + c) = o;
            }
        }
    }
}

// ---------------------------------------------------------------------------
// Causal flash attention, fp32 (unchanged from passing R1 kernel).
// ---------------------------------------------------------------------------
#define ATT_STRIDE 65
#define ATT_SMEM   (4 * 64 * ATT_STRIDE * (int)sizeof(float))

__global__ __launch_bounds__(256) void attn_kernel(
    const float* __restrict__ qkv,
    float* __restrict__ y)
{
    extern __shared__ float sm[];
    float* Qs = sm;
    float* Ks = Qs + 64 * ATT_STRIDE;
    float* Vs = Ks + 64 * ATT_STRIDE;
    float* Ps = Vs + 64 * ATT_STRIDE;

    const int qt  = blockIdx.x;            // 0..31
    const int bh  = blockIdx.y;            // 0..63
    const int b   = bh >> 4;
    const int h   = bh & 15;
    const int tid = threadIdx.x;
    const int tx  = tid & 15;
    const int ty  = tid >> 4;

    const size_t rstr = 3 * DMODEL;        // qkv row stride
    const float* qbase = qkv + ((size_t)b * SEQ + qt * 64) * rstr + h * HDIM;
    const float* kbase = qkv + (size_t)b * SEQ * rstr + DMODEL     + h * HDIM;
    const float* vbase = qkv + (size_t)b * SEQ * rstr + 2 * DMODEL + h * HDIM;

#pragma unroll
    for (int i = 0; i < 4; i++) {
        int idx = tid + i * 256;
        int r = idx >> 4, c4 = (idx & 15) * 4;
        float4 v = *reinterpret_cast<const float4*>(qbase + (size_t)r * rstr + c4);
        Qs[r * ATT_STRIDE + c4 + 0] = v.x * 0.125f;
        Qs[r * ATT_STRIDE + c4 + 1] = v.y * 0.125f;
        Qs[r * ATT_STRIDE + c4 + 2] = v.z * 0.125f;
        Qs[r * ATT_STRIDE + c4 + 3] = v.w * 0.125f;
    }

    float m[4], l[4], o[4][4];
#pragma unroll
    for (int i = 0; i < 4; i++) {
        m[i] = -1e30f; l[i] = 0.f;
#pragma unroll
        for (int j = 0; j < 4; j++) o[i][j] = 0.f;
    }

    for (int kt = 0; kt <= qt; kt++) {
        __syncthreads();
#pragma unroll
        for (int i = 0; i < 4; i++) {
            int idx = tid + i * 256;
            int r = idx >> 4, c4 = (idx & 15) * 4;
            size_t grow = (size_t)(kt * 64 + r) * rstr + c4;
            float4 kv4 = *reinterpret_cast<const float4*>(kbase + grow);
            Ks[r * ATT_STRIDE + c4 + 0] = kv4.x;
            Ks[r * ATT_STRIDE + c4 + 1] = kv4.y;
            Ks[r * ATT_STRIDE + c4 + 2] = kv4.z;
            Ks[r * ATT_STRIDE + c4 + 3] = kv4.w;
            float4 vv4 = *reinterpret_cast<const float4*>(vbase + grow);
            Vs[r * ATT_STRIDE + c4 + 0] = vv4.x;
            Vs[r * ATT_STRIDE + c4 + 1] = vv4.y;
            Vs[r * ATT_STRIDE + c4 + 2] = vv4.z;
            Vs[r * ATT_STRIDE + c4 + 3] = vv4.w;
        }
        __syncthreads();

        float s[4][4];
#pragma unroll
        for (int i = 0; i < 4; i++)
#pragma unroll
            for (int j = 0; j < 4; j++) s[i][j] = 0.f;
#pragma unroll 8
        for (int k = 0; k < 64; k++) {
            float qr[4], kr[4];
#pragma unroll
            for (int i = 0; i < 4; i++) qr[i] = Qs[(ty * 4 + i) * ATT_STRIDE + k];
#pragma unroll
            for (int j = 0; j < 4; j++) kr[j] = Ks[(tx * 4 + j) * ATT_STRIDE + k];
#pragma unroll
            for (int i = 0; i < 4; i++)
#pragma unroll
                for (int j = 0; j < 4; j++) s[i][j] = fmaf(qr[i], kr[j], s[i][j]);
        }

        if (kt == qt) {
#pragma unroll
            for (int i = 0; i < 4; i++)
#pragma unroll
                for (int j = 0; j < 4; j++)
                    if (tx * 4 + j > ty * 4 + i) s[i][j] = -1e30f;
        }

#pragma unroll
        for (int i = 0; i < 4; i++) {
            float mr = fmaxf(fmaxf(s[i][0], s[i][1]), fmaxf(s[i][2], s[i][3]));
#pragma unroll
            for (int off = 8; off > 0; off >>= 1)
                mr = fmaxf(mr, __shfl_xor_sync(0xffffffffu, mr, off));
            float mn = fmaxf(m[i], mr);
            float corr = __expf(m[i] - mn);
            float psum = 0.f;
#pragma unroll
            for (int j = 0; j < 4; j++) {
                s[i][j] = __expf(s[i][j] - mn);
                psum += s[i][j];
            }
#pragma unroll
            for (int off = 8; off > 0; off >>= 1)
                psum += __shfl_xor_sync(0xffffffffu, psum, off);
            l[i] = l[i] * corr + psum;
            m[i] = mn;
#pragma unroll
            for (int j = 0; j < 4; j++) {
                o[i][j] *= corr;
                Ps[(ty * 4 + i) * ATT_STRIDE + tx * 4 + j] = s[i][j];
            }
        }
        __syncthreads();

#pragma unroll 8
        for (int k = 0; k < 64; k++) {
            float pr[4], vr[4];
#pragma unroll
            for (int i = 0; i < 4; i++) pr[i] = Ps[(ty * 4 + i) * ATT_STRIDE + k];
#pragma unroll
            for (int j = 0; j < 4; j++) vr[j] = Vs[k * ATT_STRIDE + tx * 4 + j];
#pragma unroll
            for (int i = 0; i < 4; i++)
#pragma unroll
                for (int j = 0; j < 4; j++) o[i][j] = fmaf(pr[i], vr[j], o[i][j]);
        }
    }

#pragma unroll
    for (int i = 0; i < 4; i++) {
        float inv = 1.0f / l[i];
        size_t row = (size_t)b * SEQ + qt * 64 + ty * 4 + i;
#pragma unroll
        for (int j = 0; j < 4; j++)
            y[row * DMODEL + h * HDIM + tx * 4 + j] = o[i][j] * inv;
    }
}

// ---------------------------------------------------------------------------
// Launch
// ---------------------------------------------------------------------------
extern "C" void kernel_launch(void* const* d_in, const int* in_sizes, int n_in,
                              void* d_out, int out_size)
{
    const float* x      = (const float*)d_in[0];
    const float* w_attn = (const float*)d_in[1];
    const float* w_o    = (const float*)d_in[2];
    const float* ln1_g  = (const float*)d_in[3];
    const float* ln1_b  = (const float*)d_in[4];
    const float* ln2_g  = (const float*)d_in[5];
    const float* ln2_b  = (const float*)d_in[6];
    const float* w_fc   = (const float*)d_in[7];
    const float* b_fc   = (const float*)d_in[8];
    const float* w_proj = (const float*)d_in[9];
    const float* b_proj = (const float*)d_in[10];
    float* out = (float*)d_out;

    float *ln, *qkvp, *yp, *x1, *hp;
    cudaGetSymbolAddress((void**)&ln,   g_ln);
    cudaGetSymbolAddress((void**)&qkvp, g_qkv);
    cudaGetSymbolAddress((void**)&yp,   g_y);
    cudaGetSymbolAddress((void**)&x1,   g_x1);
    cudaGetSymbolAddress((void**)&hp,   g_h);

    cudaFuncSetAttribute(attn_kernel,
                         cudaFuncAttributeMaxDynamicSharedMemorySize, ATT_SMEM);

    // 1) ln1
    ln_kernel<<<ROWS, 256>>>(x, ln1_g, ln1_b, ln);
    // 2) qkv = ln1 @ w_attn        [8192 x 3072]
    tf32_gemm<0><<<dim3(3 * DMODEL / 128, ROWS / 128), 256>>>(
        ROWS, 3 * DMODEL, DMODEL, ln, w_attn, nullptr, nullptr, qkvp);
    // 3) attention -> y
    attn_kernel<<<dim3(SEQ / 64, BATCH * NHEAD), 256, ATT_SMEM>>>(qkvp, yp);
    // 4) x1 = x + y @ w_o
    tf32_gemm<1><<<dim3(DMODEL / 128, ROWS / 128), 256>>>(
        ROWS, DMODEL, DMODEL, yp, w_o, nullptr, x, x1);
    // 5) ln2
    ln_kernel<<<ROWS, 256>>>(x1, ln2_g, ln2_b, ln);
    // 6) h = gelu(ln2 @ w_fc + b_fc)   [8192 x 4096]
    tf32_gemm<2><<<dim3(4 * DMODEL / 128, ROWS / 128), 256>>>(
        ROWS, 4 * DMODEL, DMODEL, ln, w_fc, b_fc, nullptr, hp);
    // 7) out = x1 + h @ w_proj + b_proj
    tf32_gemm<3><<<dim3(DMODEL / 128, ROWS / 128), 256>>>(
        ROWS, DMODEL, 4 * DMODEL, hp, w_proj, b_proj, x1, out);
}